// round 14
// baseline (speedup 1.0000x reference)
#include <cuda_runtime.h>
#include <cuda_bf16.h>
#include <cstdint>

// ISTA deconvolution via mma.sync bf16 (round 14).
// R13 (147.8us, L1=78% LDSM-bound) -> widen M per warp to 32 (2 m-tiles):
// B fragment loads amortize over 24 MMAs instead of 12 per k-step.
//   CTA: 256 output cols x 32 batch rows, 8 warps x 32 cols each.
//   A: 32x160 band Toeplitz  A[mi][kk] = w[kk-mi-1]  (shared by all warps)
//   B[jjg][n] = signal[r0+n][c0-64+jjg], jjg = 32w + kk in [0,384)
//   D[mi,n] = sum_d w[d] * signal[r0+n][(c0+32w+mi)+d-63]   (TF SAME)
// Stage0: w = delta63 - h -> residual, stored TRANSPOSED g_resid[col][row].
// Stage1: w = h reversed  -> u; ISTA closed form x=T*sign(su)*max(|su|-L,0).
// Split bf16 (hi+lo), combos hh+hl+lh, fp32 accumulate (rel_err ~6e-6).

#define LDIM 4096
#define BDIM 4096
#define KW   128
#define LAMBDA 0.1f
#define TITER  5.0f
#define NTH  256
#define ROWS 32
#define COLS 256

#define AS   168                     // A stride (bf16): 336B = 21*16 -> ldsm conflict-free
#define A_BYTES (32 * AS * 2)        // 10752
#define BJJ  384
#define BS0  392                     // mode0 [n][jj] stride: 784B = 49*16
#define BS1  40                      // mode1 [jj][n] stride: 80B = 5*16
#define B0_BYTES (ROWS * BS0 * 2)    // 25088
#define B1_BYTES (BJJ * BS1 * 2)     // 30720
#define SM_AHI 0
#define SM_ALO A_BYTES
#define SM_BHI (2 * A_BYTES)         // 21504
#define SMT0 (SM_BHI + 2 * B0_BYTES) // 71680
#define SMT1 (SM_BHI + 2 * B1_BYTES) // 82944

__device__ float g_resid[(size_t)BDIM * LDIM];   // residual, TRANSPOSED [col][row]

__device__ __forceinline__ uint32_t smem_u32(const void* p) {
    uint32_t a;
    asm("{ .reg .u64 t; cvta.to.shared.u64 t, %1; cvt.u32.u64 %0, t; }"
        : "=r"(a) : "l"(p));
    return a;
}
__device__ __forceinline__ void ldsm_x4(uint32_t* r, uint32_t addr) {
    asm volatile("ldmatrix.sync.aligned.m8n8.x4.shared.b16 {%0,%1,%2,%3}, [%4];"
        : "=r"(r[0]), "=r"(r[1]), "=r"(r[2]), "=r"(r[3]) : "r"(addr));
}
__device__ __forceinline__ void ldsm_x4_t(uint32_t* r, uint32_t addr) {
    asm volatile("ldmatrix.sync.aligned.m8n8.x4.trans.shared.b16 {%0,%1,%2,%3}, [%4];"
        : "=r"(r[0]), "=r"(r[1]), "=r"(r[2]), "=r"(r[3]) : "r"(addr));
}
__device__ __forceinline__ void mma_bf16(float* c, const uint32_t* a, const uint32_t* b) {
    asm volatile(
        "mma.sync.aligned.m16n8k16.row.col.f32.bf16.bf16.f32 "
        "{%0,%1,%2,%3}, {%4,%5,%6,%7}, {%8,%9}, {%0,%1,%2,%3};"
        : "+f"(c[0]), "+f"(c[1]), "+f"(c[2]), "+f"(c[3])
        : "r"(a[0]), "r"(a[1]), "r"(a[2]), "r"(a[3]), "r"(b[0]), "r"(b[1]));
}
__device__ __forceinline__ void split_bf16(float v, __nv_bfloat16& hi, __nv_bfloat16& lo) {
    hi = __float2bfloat16(v);
    lo = __float2bfloat16(v - __bfloat162float(hi));
}

template <int MODE>
__global__ __launch_bounds__(NTH, 2)
void conv_mma_kernel(const float* __restrict__ y,
                     const float* __restrict__ h,
                     const float* __restrict__ step,
                     float* __restrict__ out)
{
    extern __shared__ __align__(16) char smem[];
    constexpr int B_BYTES = (MODE == 0) ? B0_BYTES : B1_BYTES;
    const int tid = threadIdx.x, w = tid >> 5, lane = tid & 31;
    const int c0 = blockIdx.x * COLS;
    const int r0 = blockIdx.y * ROWS;
    __nv_bfloat16* Ahi = (__nv_bfloat16*)(smem + SM_AHI);
    __nv_bfloat16* Alo = (__nv_bfloat16*)(smem + SM_ALO);
    __nv_bfloat16* Bhi = (__nv_bfloat16*)(smem + SM_BHI);
    __nv_bfloat16* Blo = (__nv_bfloat16*)(smem + SM_BHI + B_BYTES);

    // ---- Toeplitz A (32 x 160), split hi/lo ----
    for (int idx = tid; idx < 32 * 160; idx += NTH) {
        int mi = idx / 160, jj = idx - mi * 160;
        int d = jj - mi - 1;
        float wv = 0.0f;
        if (0 <= d && d < KW)
            wv = (MODE == 0) ? ((d == 63) ? 1.0f : 0.0f) - __ldg(h + d)
                             : __ldg(h + (KW - 1) - d);
        __nv_bfloat16 hi, lo;
        split_bf16(wv, hi, lo);
        Ahi[mi * AS + jj] = hi;
        Alo[mi * AS + jj] = lo;
    }

    // ---- Stage B tile (384 jj x 32 n), split hi/lo ----
    if (MODE == 0) {
        // B[n][jj] = y[r0+n][c0-64+jj]
#pragma unroll
        for (int it = 0; it < 12; it++) {
            int idx = tid + it * NTH;            // 32 * 96 float4 items
            int n = idx / 96, q = idx - 96 * (idx / 96);
            int gc = c0 - 64 + 4 * q;
            const float* base = y + (size_t)(r0 + n) * LDIM;
            float4 f;
            if ((unsigned)gc <= (unsigned)(LDIM - 4)) {
                f = *(const float4*)(base + gc);
            } else {
                f.x = ((unsigned)(gc + 0) < LDIM) ? base[gc + 0] : 0.0f;
                f.y = ((unsigned)(gc + 1) < LDIM) ? base[gc + 1] : 0.0f;
                f.z = ((unsigned)(gc + 2) < LDIM) ? base[gc + 2] : 0.0f;
                f.w = ((unsigned)(gc + 3) < LDIM) ? base[gc + 3] : 0.0f;
            }
            __nv_bfloat16 h0, l0, h1, l1, h2, l2, h3, l3;
            split_bf16(f.x, h0, l0); split_bf16(f.y, h1, l1);
            split_bf16(f.z, h2, l2); split_bf16(f.w, h3, l3);
            __nv_bfloat162* dh = (__nv_bfloat162*)(Bhi + n * BS0 + 4 * q);
            __nv_bfloat162* dl = (__nv_bfloat162*)(Blo + n * BS0 + 4 * q);
            dh[0] = __halves2bfloat162(h0, h1); dh[1] = __halves2bfloat162(h2, h3);
            dl[0] = __halves2bfloat162(l0, l1); dl[1] = __halves2bfloat162(l2, l3);
        }
    } else {
        // B[jj][n] = g_resid[c0-64+jj][r0+n]
#pragma unroll
        for (int it = 0; it < 12; it++) {
            int idx = tid + it * NTH;            // 384 * 8 float4 items
            int jj = idx >> 3, q = idx & 7;
            int gc = c0 - 64 + jj;
            float4 f = make_float4(0.f, 0.f, 0.f, 0.f);
            if ((unsigned)gc < (unsigned)LDIM)
                f = *(const float4*)(g_resid + (size_t)gc * LDIM + r0 + 4 * q);
            __nv_bfloat16 h0, l0, h1, l1, h2, l2, h3, l3;
            split_bf16(f.x, h0, l0); split_bf16(f.y, h1, l1);
            split_bf16(f.z, h2, l2); split_bf16(f.w, h3, l3);
            __nv_bfloat162* dh = (__nv_bfloat162*)(Bhi + jj * BS1 + 4 * q);
            __nv_bfloat162* dl = (__nv_bfloat162*)(Blo + jj * BS1 + 4 * q);
            dh[0] = __halves2bfloat162(h0, h1); dh[1] = __halves2bfloat162(h2, h3);
            dl[0] = __halves2bfloat162(l0, l1); dl[1] = __halves2bfloat162(l2, l3);
        }
    }
    __syncthreads();

    // ---- MMA mainloop: 10 ksteps; per s: 8 LDSM -> 24 MMAs (8 acc chains) ----
    float acc[2][4][4];
#pragma unroll
    for (int m = 0; m < 2; m++)
#pragma unroll
        for (int i = 0; i < 4; i++)
#pragma unroll
            for (int j = 0; j < 4; j++) acc[m][i][j] = 0.0f;

    const uint32_t sb = smem_u32(smem);
    const uint32_t aCol = (lane & 16) ? 8u : 0u;
    const uint32_t aHi0 = sb + SM_AHI + ((((lane & 15) +  0) * AS + aCol) << 1);
    const uint32_t aHi1 = sb + SM_AHI + ((((lane & 15) + 16) * AS + aCol) << 1);
    uint32_t bA0, bA1;
    if (MODE == 0) {
        uint32_t b0n = (lane & 7) + ((lane & 16) ? 8 : 0);
        uint32_t b0j = (lane & 8) ? 8 : 0;
        bA0 = sb + SM_BHI + (((0 + b0n) * BS0 + b0j) << 1);
        bA1 = sb + SM_BHI + (((16 + b0n) * BS0 + b0j) << 1);
    } else {
        uint32_t b1j = lane & 15, b1n = (lane & 16) ? 8 : 0;
        bA0 = sb + SM_BHI + ((b1j * BS1 + 0 + b1n) << 1);
        bA1 = sb + SM_BHI + ((b1j * BS1 + 16 + b1n) << 1);
    }

#pragma unroll
    for (int s = 0; s < 10; s++) {
        uint32_t ah0[4], ah1[4], al0[4], al1[4];
        uint32_t bh0[4], bh1[4], bl0[4], bl1[4];
        ldsm_x4(ah0, aHi0 + 32u * s);
        ldsm_x4(ah1, aHi1 + 32u * s);
        ldsm_x4(al0, aHi0 + (uint32_t)A_BYTES + 32u * s);
        ldsm_x4(al1, aHi1 + (uint32_t)A_BYTES + 32u * s);
        const uint32_t jj0 = 32u * w + 16u * s;
        const uint32_t bo = (MODE == 0) ? (jj0 << 1) : (jj0 * BS1 * 2u);
        if (MODE == 0) {
            ldsm_x4(bh0, bA0 + bo); ldsm_x4(bh1, bA1 + bo);
            ldsm_x4(bl0, bA0 + bo + B_BYTES); ldsm_x4(bl1, bA1 + bo + B_BYTES);
        } else {
            ldsm_x4_t(bh0, bA0 + bo); ldsm_x4_t(bh1, bA1 + bo);
            ldsm_x4_t(bl0, bA0 + bo + B_BYTES); ldsm_x4_t(bl1, bA1 + bo + B_BYTES);
        }
        // combo-major, 8 independent chains per combo
        mma_bf16(acc[0][0], ah0, bh0); mma_bf16(acc[0][1], ah0, bh0 + 2);
        mma_bf16(acc[0][2], ah0, bh1); mma_bf16(acc[0][3], ah0, bh1 + 2);
        mma_bf16(acc[1][0], ah1, bh0); mma_bf16(acc[1][1], ah1, bh0 + 2);
        mma_bf16(acc[1][2], ah1, bh1); mma_bf16(acc[1][3], ah1, bh1 + 2);

        mma_bf16(acc[0][0], ah0, bl0); mma_bf16(acc[0][1], ah0, bl0 + 2);
        mma_bf16(acc[0][2], ah0, bl1); mma_bf16(acc[0][3], ah0, bl1 + 2);
        mma_bf16(acc[1][0], ah1, bl0); mma_bf16(acc[1][1], ah1, bl0 + 2);
        mma_bf16(acc[1][2], ah1, bl1); mma_bf16(acc[1][3], ah1, bl1 + 2);

        mma_bf16(acc[0][0], al0, bh0); mma_bf16(acc[0][1], al0, bh0 + 2);
        mma_bf16(acc[0][2], al0, bh1); mma_bf16(acc[0][3], al0, bh1 + 2);
        mma_bf16(acc[1][0], al1, bh0); mma_bf16(acc[1][1], al1, bh0 + 2);
        mma_bf16(acc[1][2], al1, bh1); mma_bf16(acc[1][3], al1, bh1 + 2);
    }

    // ---- Epilogue ----
    const int mi = lane >> 2;
    const int nf = (lane & 3) * 2;
    if (MODE == 0) {
#pragma unroll
        for (int m = 0; m < 2; m++) {
            int mg = c0 + 32 * w + 16 * m + mi;
#pragma unroll
            for (int t = 0; t < 4; t++) {
                int rg = r0 + 8 * t + nf;
                *(float2*)(g_resid + (size_t)mg * LDIM + rg) =
                    make_float2(acc[m][t][0], acc[m][t][1]);
                *(float2*)(g_resid + (size_t)(mg + 8) * LDIM + rg) =
                    make_float2(acc[m][t][2], acc[m][t][3]);
            }
        }
    } else {
        // SMEM transpose -> coalesced float4 stores
        __syncthreads();
        float* smT = (float*)smem;    // [32][264]
#pragma unroll
        for (int m = 0; m < 2; m++) {
            int cw = 32 * w + 16 * m + mi;
#pragma unroll
            for (int t = 0; t < 4; t++) {
                smT[(8 * t + nf) * 264 + cw]         = acc[m][t][0];
                smT[(8 * t + nf + 1) * 264 + cw]     = acc[m][t][1];
                smT[(8 * t + nf) * 264 + cw + 8]     = acc[m][t][2];
                smT[(8 * t + nf + 1) * 264 + cw + 8] = acc[m][t][3];
            }
        }
        __syncthreads();
        const float sv = __ldg(step);
        const int n = tid >> 3, cq = tid & 7;     // 8 threads per row
        const float* srow = smT + n * 264 + 32 * cq;
        float4* orow = (float4*)(out + (size_t)(r0 + n) * LDIM + c0 + 32 * cq);
#pragma unroll
        for (int i = 0; i < 8; i++) {
            float a0 = sv * srow[4 * i + 0];
            float a1 = sv * srow[4 * i + 1];
            float a2 = sv * srow[4 * i + 2];
            float a3 = sv * srow[4 * i + 3];
            orow[i] = make_float4(
                copysignf(TITER * fmaxf(fabsf(a0) - LAMBDA, 0.0f), a0),
                copysignf(TITER * fmaxf(fabsf(a1) - LAMBDA, 0.0f), a1),
                copysignf(TITER * fmaxf(fabsf(a2) - LAMBDA, 0.0f), a2),
                copysignf(TITER * fmaxf(fabsf(a3) - LAMBDA, 0.0f), a3));
        }
    }
}

extern "C" void kernel_launch(void* const* d_in, const int* in_sizes, int n_in,
                              void* d_out, int out_size)
{
    const float* y = nullptr;
    const float* h = nullptr;
    const float* s = nullptr;
    for (int i = 0; i < n_in; i++) {
        if (in_sizes[i] == BDIM * LDIM)      y = (const float*)d_in[i];
        else if (in_sizes[i] == KW)          h = (const float*)d_in[i];
        else if (in_sizes[i] == 1)           s = (const float*)d_in[i];
    }
    cudaFuncSetAttribute(conv_mma_kernel<0>,
                         cudaFuncAttributeMaxDynamicSharedMemorySize, SMT0);
    cudaFuncSetAttribute(conv_mma_kernel<1>,
                         cudaFuncAttributeMaxDynamicSharedMemorySize, SMT1);
    dim3 grid(LDIM / COLS, BDIM / ROWS);   // (16, 128)
    conv_mma_kernel<0><<<grid, NTH, SMT0>>>(y, h, s, (float*)d_out);
    conv_mma_kernel<1><<<grid, NTH, SMT1>>>(y, h, s, (float*)d_out);
}

// round 15
// speedup vs baseline: 1.0937x; 1.0937x over previous
#include <cuda_runtime.h>
#include <cuda_bf16.h>
#include <cstdint>

// ISTA deconvolution (round 15): COMPOSED single 255-tap correlation on the
// R13 MMA skeleton (best shape: 16 cols/warp, 128 cols x 32 rows/CTA, occ 3).
//   u[n] = sum_e W[e] * y[n+e-126],  W = (delta63 - h) (*) h_rev  (255 taps)
// computed per-CTA from h (cheap). Removes the g_resid round trip entirely.
// Composition is EXACT for output cols [63, L-64); cols [0,64) and [L-64,L)
// are recomputed exactly by a small SIMT edge kernel that overwrites them.
// GEMM: D[mi,n] = sum_kk A[mi][kk]*B[16w+kk][n],
//   A[mi][kk] = W[kk-mi-2] (16x272 band Toeplitz, shared by all 8 warps)
//   B[jj][n]  = y[r0+n][c0-128+jj], jj in [0,384)
// Split bf16 (hi+lo), combos hh+hl+lh, fp32 accumulate.

#define LDIM 4096
#define BDIM 4096
#define KW   128
#define LAMBDA 0.1f
#define TITER  5.0f
#define NTH  256
#define ROWS 32
#define COLS 128

#define AKK 272
#define AS  280                      // A stride bf16: 560B = 35*16 conflict-free
#define A_BYTES (16 * AS * 2)        // 8960
#define BJJ 384
#define BS  392                      // B stride bf16: 784B = 49*16
#define B_BYTES (ROWS * BS * 2)      // 25088
#define SM_AHI 0
#define SM_ALO A_BYTES
#define SM_BHI (2 * A_BYTES)         // 17920
#define SM_TOTAL (SM_BHI + 2 * B_BYTES)   // 68096

__device__ __forceinline__ uint32_t smem_u32(const void* p) {
    uint32_t a;
    asm("{ .reg .u64 t; cvta.to.shared.u64 t, %1; cvt.u32.u64 %0, t; }"
        : "=r"(a) : "l"(p));
    return a;
}
__device__ __forceinline__ void ldsm_x4(uint32_t* r, uint32_t addr) {
    asm volatile("ldmatrix.sync.aligned.m8n8.x4.shared.b16 {%0,%1,%2,%3}, [%4];"
        : "=r"(r[0]), "=r"(r[1]), "=r"(r[2]), "=r"(r[3]) : "r"(addr));
}
__device__ __forceinline__ void mma_bf16(float* c, const uint32_t* a, const uint32_t* b) {
    asm volatile(
        "mma.sync.aligned.m16n8k16.row.col.f32.bf16.bf16.f32 "
        "{%0,%1,%2,%3}, {%4,%5,%6,%7}, {%8,%9}, {%0,%1,%2,%3};"
        : "+f"(c[0]), "+f"(c[1]), "+f"(c[2]), "+f"(c[3])
        : "r"(a[0]), "r"(a[1]), "r"(a[2]), "r"(a[3]), "r"(b[0]), "r"(b[1]));
}
__device__ __forceinline__ void split_bf16(float v, __nv_bfloat16& hi, __nv_bfloat16& lo) {
    hi = __float2bfloat16(v);
    lo = __float2bfloat16(v - __bfloat162float(hi));
}

__global__ __launch_bounds__(NTH, 3)
void ista_composed_kernel(const float* __restrict__ y,
                          const float* __restrict__ h,
                          const float* __restrict__ step,
                          float* __restrict__ out)
{
    extern __shared__ __align__(16) char smem[];
    __shared__ float shH[KW];
    __shared__ float shW[255];
    const int tid = threadIdx.x, w = tid >> 5, lane = tid & 31;
    const int c0 = blockIdx.x * COLS;
    const int r0 = blockIdx.y * ROWS;
    __nv_bfloat16* Ahi = (__nv_bfloat16*)(smem + SM_AHI);
    __nv_bfloat16* Alo = (__nv_bfloat16*)(smem + SM_ALO);
    __nv_bfloat16* Bhi = (__nv_bfloat16*)(smem + SM_BHI);
    __nv_bfloat16* Blo = (__nv_bfloat16*)(smem + SM_BHI + B_BYTES);

    if (tid < KW) shH[tid] = __ldg(h + tid);
    __syncthreads();

    // ---- W[e] = [63<=e<=190]*h[190-e] - sum_j h[j]*h[127-e+j] ----
    if (tid < 255) {
        int e = tid;
        int jlo = (e > 127) ? e - 127 : 0;
        int jhi = (e < 127) ? e : 127;
        float ssum = 0.0f;
        for (int j = jlo; j <= jhi; j++) ssum += shH[j] * shH[127 - e + j];
        float dterm = (e >= 63 && e <= 190) ? shH[190 - e] : 0.0f;
        shW[e] = dterm - ssum;
    }

    // ---- Stage B[jj][n] = y[r0+n][c0-128+jj], split hi/lo (while W computes) ----
#pragma unroll
    for (int it = 0; it < 12; it++) {
        int idx = tid + it * NTH;                 // 32 rows x 96 float4
        int n = idx / 96, q = idx - n * 96;
        int gc = c0 - 128 + 4 * q;                // 4-aligned
        const float* base = y + (size_t)(r0 + n) * LDIM;
        float4 f;
        if ((unsigned)gc <= (unsigned)(LDIM - 4)) {
            f = *(const float4*)(base + gc);
        } else {
            f.x = ((unsigned)(gc + 0) < LDIM) ? base[gc + 0] : 0.0f;
            f.y = ((unsigned)(gc + 1) < LDIM) ? base[gc + 1] : 0.0f;
            f.z = ((unsigned)(gc + 2) < LDIM) ? base[gc + 2] : 0.0f;
            f.w = ((unsigned)(gc + 3) < LDIM) ? base[gc + 3] : 0.0f;
        }
        __nv_bfloat16 h0, l0, h1, l1, h2, l2, h3, l3;
        split_bf16(f.x, h0, l0); split_bf16(f.y, h1, l1);
        split_bf16(f.z, h2, l2); split_bf16(f.w, h3, l3);
        __nv_bfloat162* dh = (__nv_bfloat162*)(Bhi + n * BS + 4 * q);
        __nv_bfloat162* dl = (__nv_bfloat162*)(Blo + n * BS + 4 * q);
        dh[0] = __halves2bfloat162(h0, h1); dh[1] = __halves2bfloat162(h2, h3);
        dl[0] = __halves2bfloat162(l0, l1); dl[1] = __halves2bfloat162(l2, l3);
    }
    __syncthreads();

    // ---- Build Toeplitz A (16 x 272): A[mi][kk] = W[kk-mi-2] ----
    for (int idx = tid; idx < 16 * AKK; idx += NTH) {
        int mi = idx / AKK, kk = idx - mi * AKK;
        int e = kk - mi - 2;
        float wv = ((unsigned)e < 255u) ? shW[e] : 0.0f;
        __nv_bfloat16 hi, lo;
        split_bf16(wv, hi, lo);
        Ahi[mi * AS + kk] = hi;
        Alo[mi * AS + kk] = lo;
    }
    __syncthreads();

    // ---- MMA mainloop: 17 ksteps, combo-major (R13 schedule) ----
    float acc[4][4];
#pragma unroll
    for (int i = 0; i < 4; i++)
#pragma unroll
        for (int j = 0; j < 4; j++) acc[i][j] = 0.0f;

    const uint32_t sb = smem_u32(smem);
    const uint32_t aHi = sb + SM_AHI + (((lane & 15) * AS + ((lane & 16) ? 8 : 0)) << 1);
    const uint32_t b0n = (lane & 7) + ((lane & 16) ? 8 : 0);
    const uint32_t b0j = (lane & 8) ? 8 : 0;
    const uint32_t bA0 = sb + SM_BHI + (((0 + b0n) * BS + b0j) << 1);
    const uint32_t bA1 = sb + SM_BHI + (((16 + b0n) * BS + b0j) << 1);

#pragma unroll
    for (int s = 0; s < 17; s++) {
        uint32_t ah[4], al[4], bh0[4], bh1[4], bl0[4], bl1[4];
        ldsm_x4(ah, aHi + 32u * s);
        ldsm_x4(al, aHi + (uint32_t)A_BYTES + 32u * s);
        const uint32_t bo = (16u * (w + s)) << 1;
        ldsm_x4(bh0, bA0 + bo); ldsm_x4(bh1, bA1 + bo);
        ldsm_x4(bl0, bA0 + bo + B_BYTES); ldsm_x4(bl1, bA1 + bo + B_BYTES);
        mma_bf16(acc[0], ah, bh0); mma_bf16(acc[1], ah, bh0 + 2);
        mma_bf16(acc[2], ah, bh1); mma_bf16(acc[3], ah, bh1 + 2);
        mma_bf16(acc[0], ah, bl0); mma_bf16(acc[1], ah, bl0 + 2);
        mma_bf16(acc[2], ah, bl1); mma_bf16(acc[3], ah, bl1 + 2);
        mma_bf16(acc[0], al, bh0); mma_bf16(acc[1], al, bh0 + 2);
        mma_bf16(acc[2], al, bh1); mma_bf16(acc[3], al, bh1 + 2);
    }

    // ---- Epilogue: SMEM transpose -> ISTA -> coalesced float4 stores ----
    __syncthreads();
    float* smT = (float*)smem;   // [32][132]
    const int mi = lane >> 2;
    const int nf = (lane & 3) * 2;
    const int cw = 16 * w + mi;
#pragma unroll
    for (int t = 0; t < 4; t++) {
        smT[(8 * t + nf) * 132 + cw]         = acc[t][0];
        smT[(8 * t + nf + 1) * 132 + cw]     = acc[t][1];
        smT[(8 * t + nf) * 132 + cw + 8]     = acc[t][2];
        smT[(8 * t + nf + 1) * 132 + cw + 8] = acc[t][3];
    }
    __syncthreads();
    const float sv = __ldg(step);
    const int n = tid >> 3, cq = tid & 7;
    const float* srow = smT + n * 132 + 16 * cq;
    float4* orow = (float4*)(out + (size_t)(r0 + n) * LDIM + c0 + 16 * cq);
#pragma unroll
    for (int i = 0; i < 4; i++) {
        float a0 = sv * srow[4 * i + 0];
        float a1 = sv * srow[4 * i + 1];
        float a2 = sv * srow[4 * i + 2];
        float a3 = sv * srow[4 * i + 3];
        orow[i] = make_float4(
            copysignf(TITER * fmaxf(fabsf(a0) - LAMBDA, 0.0f), a0),
            copysignf(TITER * fmaxf(fabsf(a1) - LAMBDA, 0.0f), a1),
            copysignf(TITER * fmaxf(fabsf(a2) - LAMBDA, 0.0f), a2),
            copysignf(TITER * fmaxf(fabsf(a3) - LAMBDA, 0.0f), a3));
    }
}

// ============ Edge-fix kernel: exact 2-stage for cols [0,64) & [4032,4096) ===
#define EYS 324     // y window stride (floats), 320 cols: [64,256) = data
#define ERS 260     // resid window stride, cols [64,192) = resid data

__global__ __launch_bounds__(NTH, 2)
void ista_edge_kernel(const float* __restrict__ y,
                      const float* __restrict__ h,
                      const float* __restrict__ step,
                      float* __restrict__ out)
{
    extern __shared__ __align__(16) float esm[];
    __shared__ float shH[KW];
    float* yw = esm;                  // [32][EYS]
    float* rw = esm + 32 * EYS;       // [32][ERS], zero-padded
    const int tid = threadIdx.x;
    const int side = blockIdx.x;      // 0: cols [0,64); 1: cols [4032,4096)
    const int r0 = 32 * blockIdx.y;
    const int ybase = side ? (LDIM - 192) : 0;   // 3904 or 0
    const int off = side ? 64 : 0;
    const int nbase = side ? (LDIM - 64) : 0;

    if (tid < KW) shH[tid] = __ldg(h + tid);
    // y window: col in [0,320), data at [64,256) <- y[ybase .. ybase+192)
    for (int idx = tid; idx < 32 * 320; idx += NTH) {
        int r = idx / 320, col = idx - 320 * r;
        float v = 0.0f;
        if (col >= 64 && col < 256) v = y[(size_t)(r0 + r) * LDIM + ybase + col - 64];
        yw[r * EYS + col] = v;
    }
    // zero resid window (margins must be zero)
    for (int idx = tid; idx < 32 * ERS; idx += NTH) rw[idx] = 0.0f;
    __syncthreads();

    // resid[m] (m local in [0,128)) = y[gm] - sum_d h[d]*y[gm+d-63], 8-blocked
    for (int g = tid; g < 32 * 16; g += NTH) {
        int r = g >> 4, m0 = (g & 15) * 8;
        const float* yr = yw + r * EYS + m0 + 1 + off;    // yr[d+j] = y col (m0+j)+d-63
        float acc[8];
#pragma unroll
        for (int j = 0; j < 8; j++) acc[j] = yw[r * EYS + m0 + j + 64 + off];
        float xw[8];
#pragma unroll
        for (int j = 0; j < 8; j++) xw[j] = yr[j];
#pragma unroll 8
        for (int d = 0; d < KW; d++) {
            float hd = shH[d];
#pragma unroll
            for (int j = 0; j < 8; j++) acc[j] -= hd * xw[(d + j) & 7];
            xw[d & 7] = yr[d + 8];
        }
#pragma unroll
        for (int j = 0; j < 8; j++) rw[r * ERS + m0 + j + 64] = acc[j];
    }
    __syncthreads();

    // u[n] = sum_d1 h[127-d1]*resid_pad[n+d1-63]; ring over padded rw
    const float sv = __ldg(step);
    {
        int g = tid;                      // 32 x 8 groups == NTH
        int r = g >> 3, nc0 = (g & 7) * 8;
        // padded col at d1=0,j=0: side0: nc0-63+64 = nc0+1; side1: nc0+1+64
        const float* rr = rw + r * ERS + nc0 + 1 + off;
        float acc[8];
#pragma unroll
        for (int j = 0; j < 8; j++) acc[j] = 0.0f;
        float xw[8];
#pragma unroll
        for (int j = 0; j < 8; j++) xw[j] = rr[j];
#pragma unroll 8
        for (int d = 0; d < KW; d++) {
            float hd = shH[127 - d];
#pragma unroll
            for (int j = 0; j < 8; j++) acc[j] += hd * xw[(d + j) & 7];
            xw[d & 7] = rr[d + 8];
        }
        float o[8];
#pragma unroll
        for (int j = 0; j < 8; j++) {
            float a = sv * acc[j];
            o[j] = copysignf(TITER * fmaxf(fabsf(a) - LAMBDA, 0.0f), a);
        }
        float4* op = (float4*)(out + (size_t)(r0 + r) * LDIM + nbase + nc0);
        op[0] = make_float4(o[0], o[1], o[2], o[3]);
        op[1] = make_float4(o[4], o[5], o[6], o[7]);
    }
}

extern "C" void kernel_launch(void* const* d_in, const int* in_sizes, int n_in,
                              void* d_out, int out_size)
{
    const float* y = nullptr;
    const float* h = nullptr;
    const float* s = nullptr;
    for (int i = 0; i < n_in; i++) {
        if (in_sizes[i] == BDIM * LDIM)      y = (const float*)d_in[i];
        else if (in_sizes[i] == KW)          h = (const float*)d_in[i];
        else if (in_sizes[i] == 1)           s = (const float*)d_in[i];
    }
    cudaFuncSetAttribute(ista_composed_kernel,
                         cudaFuncAttributeMaxDynamicSharedMemorySize, SM_TOTAL);
    int edge_smem = (32 * EYS + 32 * ERS) * 4;
    cudaFuncSetAttribute(ista_edge_kernel,
                         cudaFuncAttributeMaxDynamicSharedMemorySize, edge_smem);
    dim3 grid(LDIM / COLS, BDIM / ROWS);   // (32, 128)
    ista_composed_kernel<<<grid, NTH, SM_TOTAL>>>(y, h, s, (float*)d_out);
    ista_edge_kernel<<<dim3(2, BDIM / 32), NTH, edge_smem>>>(y, h, s, (float*)d_out);
}

// round 16
// speedup vs baseline: 1.0963x; 1.0024x over previous
#include <cuda_runtime.h>
#include <cuda_bf16.h>
#include <cstdint>

// ISTA deconvolution (round 16): composed 255-tap correlation (R15, verified)
// with the edge correction FOLDED INTO the epilogue of the edge CTAs as a
// low-rank fp32 update — the 29us serialized edge kernel is gone.
//   u[n] = sum_e W[e]*y_pad[n+e-126],  W = (delta63 - h) (*) h_rev
// Edge mismatch (pad-truncation of the intermediate residual) affects only
// n in [0,63) and [L-64,L):
//   left : rext[mm] = -sum_j h[j+mm+63]*y[j]            (mm in [1,63])
//          du[n]    = -sum_{mm=1..63-n} h[64+n+mm]*rext[mm]
//   right: rext[mm] = -sum_t h[62-mm-t]*y[L-1-t]        (mm in [0,62])
//          du[nn]   = -sum_{mm=0..min(nn,62)} h[nn-mm]*rext[mm]
// GEMM (R13 shape, occ 3): A[mi][kk]=W[kk-mi-2] 16x272 Toeplitz, shared;
// B[jj][n]=y[r0+n][c0-128+jj]; split bf16 (hi+lo), combos hh+hl+lh, fp32 acc.

#define LDIM 4096
#define BDIM 4096
#define KW   128
#define LAMBDA 0.1f
#define TITER  5.0f
#define NTH  256
#define ROWS 32
#define COLS 128

#define AKK 272
#define AS  280                      // A stride bf16: 560B = 35*16 conflict-free
#define A_BYTES (16 * AS * 2)        // 8960
#define BS  392                      // B stride bf16: 784B = 49*16
#define B_BYTES (ROWS * BS * 2)      // 25088
#define SM_AHI 0
#define SM_ALO A_BYTES
#define SM_BHI (2 * A_BYTES)         // 17920
#define SM_TOTAL (SM_BHI + 2 * B_BYTES)   // 68096

__device__ __forceinline__ uint32_t smem_u32(const void* p) {
    uint32_t a;
    asm("{ .reg .u64 t; cvta.to.shared.u64 t, %1; cvt.u32.u64 %0, t; }"
        : "=r"(a) : "l"(p));
    return a;
}
__device__ __forceinline__ void ldsm_x4(uint32_t* r, uint32_t addr) {
    asm volatile("ldmatrix.sync.aligned.m8n8.x4.shared.b16 {%0,%1,%2,%3}, [%4];"
        : "=r"(r[0]), "=r"(r[1]), "=r"(r[2]), "=r"(r[3]) : "r"(addr));
}
__device__ __forceinline__ void mma_bf16(float* c, const uint32_t* a, const uint32_t* b) {
    asm volatile(
        "mma.sync.aligned.m16n8k16.row.col.f32.bf16.bf16.f32 "
        "{%0,%1,%2,%3}, {%4,%5,%6,%7}, {%8,%9}, {%0,%1,%2,%3};"
        : "+f"(c[0]), "+f"(c[1]), "+f"(c[2]), "+f"(c[3])
        : "r"(a[0]), "r"(a[1]), "r"(a[2]), "r"(a[3]), "r"(b[0]), "r"(b[1]));
}
__device__ __forceinline__ void split_bf16(float v, __nv_bfloat16& hi, __nv_bfloat16& lo) {
    hi = __float2bfloat16(v);
    lo = __float2bfloat16(v - __bfloat162float(hi));
}

__global__ __launch_bounds__(NTH, 3)
void ista_composed_kernel(const float* __restrict__ y,
                          const float* __restrict__ h,
                          const float* __restrict__ step,
                          float* __restrict__ out)
{
    extern __shared__ __align__(16) char smem[];
    __shared__ float shH[KW];
    __shared__ float shW[255];
    const int tid = threadIdx.x, w = tid >> 5, lane = tid & 31;
    const int c0 = blockIdx.x * COLS;
    const int r0 = blockIdx.y * ROWS;
    __nv_bfloat16* Ahi = (__nv_bfloat16*)(smem + SM_AHI);
    __nv_bfloat16* Alo = (__nv_bfloat16*)(smem + SM_ALO);
    __nv_bfloat16* Bhi = (__nv_bfloat16*)(smem + SM_BHI);
    __nv_bfloat16* Blo = (__nv_bfloat16*)(smem + SM_BHI + B_BYTES);

    if (tid < KW) shH[tid] = __ldg(h + tid);
    __syncthreads();

    // ---- W[e] = [63<=e<=190]*h[190-e] - sum_j h[j]*h[127-e+j] ----
    if (tid < 255) {
        int e = tid;
        int jlo = (e > 127) ? e - 127 : 0;
        int jhi = (e < 127) ? e : 127;
        float ssum = 0.0f;
        for (int j = jlo; j <= jhi; j++) ssum += shH[j] * shH[127 - e + j];
        float dterm = (e >= 63 && e <= 190) ? shH[190 - e] : 0.0f;
        shW[e] = dterm - ssum;
    }

    // ---- Stage B[jj][n] = y[r0+n][c0-128+jj], split hi/lo ----
#pragma unroll
    for (int it = 0; it < 12; it++) {
        int idx = tid + it * NTH;                 // 32 rows x 96 float4
        int n = idx / 96, q = idx - n * 96;
        int gc = c0 - 128 + 4 * q;
        const float* base = y + (size_t)(r0 + n) * LDIM;
        float4 f;
        if ((unsigned)gc <= (unsigned)(LDIM - 4)) {
            f = *(const float4*)(base + gc);
        } else {
            f.x = ((unsigned)(gc + 0) < LDIM) ? base[gc + 0] : 0.0f;
            f.y = ((unsigned)(gc + 1) < LDIM) ? base[gc + 1] : 0.0f;
            f.z = ((unsigned)(gc + 2) < LDIM) ? base[gc + 2] : 0.0f;
            f.w = ((unsigned)(gc + 3) < LDIM) ? base[gc + 3] : 0.0f;
        }
        __nv_bfloat16 h0, l0, h1, l1, h2, l2, h3, l3;
        split_bf16(f.x, h0, l0); split_bf16(f.y, h1, l1);
        split_bf16(f.z, h2, l2); split_bf16(f.w, h3, l3);
        __nv_bfloat162* dh = (__nv_bfloat162*)(Bhi + n * BS + 4 * q);
        __nv_bfloat162* dl = (__nv_bfloat162*)(Blo + n * BS + 4 * q);
        dh[0] = __halves2bfloat162(h0, h1); dh[1] = __halves2bfloat162(h2, h3);
        dl[0] = __halves2bfloat162(l0, l1); dl[1] = __halves2bfloat162(l2, l3);
    }
    __syncthreads();

    // ---- Build Toeplitz A (16 x 272): A[mi][kk] = W[kk-mi-2] ----
    for (int idx = tid; idx < 16 * AKK; idx += NTH) {
        int mi = idx / AKK, kk = idx - mi * AKK;
        int e = kk - mi - 2;
        float wv = ((unsigned)e < 255u) ? shW[e] : 0.0f;
        __nv_bfloat16 hi, lo;
        split_bf16(wv, hi, lo);
        Ahi[mi * AS + kk] = hi;
        Alo[mi * AS + kk] = lo;
    }
    __syncthreads();

    // ---- MMA mainloop: 17 ksteps, combo-major (R13 schedule) ----
    float acc[4][4];
#pragma unroll
    for (int i = 0; i < 4; i++)
#pragma unroll
        for (int j = 0; j < 4; j++) acc[i][j] = 0.0f;

    const uint32_t sb = smem_u32(smem);
    const uint32_t aHi = sb + SM_AHI + (((lane & 15) * AS + ((lane & 16) ? 8 : 0)) << 1);
    const uint32_t b0n = (lane & 7) + ((lane & 16) ? 8 : 0);
    const uint32_t b0j = (lane & 8) ? 8 : 0;
    const uint32_t bA0 = sb + SM_BHI + (((0 + b0n) * BS + b0j) << 1);
    const uint32_t bA1 = sb + SM_BHI + (((16 + b0n) * BS + b0j) << 1);

#pragma unroll
    for (int s = 0; s < 17; s++) {
        uint32_t ah[4], al[4], bh0[4], bh1[4], bl0[4], bl1[4];
        ldsm_x4(ah, aHi + 32u * s);
        ldsm_x4(al, aHi + (uint32_t)A_BYTES + 32u * s);
        const uint32_t bo = (16u * (w + s)) << 1;
        ldsm_x4(bh0, bA0 + bo); ldsm_x4(bh1, bA1 + bo);
        ldsm_x4(bl0, bA0 + bo + B_BYTES); ldsm_x4(bl1, bA1 + bo + B_BYTES);
        mma_bf16(acc[0], ah, bh0); mma_bf16(acc[1], ah, bh0 + 2);
        mma_bf16(acc[2], ah, bh1); mma_bf16(acc[3], ah, bh1 + 2);
        mma_bf16(acc[0], ah, bl0); mma_bf16(acc[1], ah, bl0 + 2);
        mma_bf16(acc[2], ah, bl1); mma_bf16(acc[3], ah, bl1 + 2);
        mma_bf16(acc[0], al, bh0); mma_bf16(acc[1], al, bh0 + 2);
        mma_bf16(acc[2], al, bh1); mma_bf16(acc[3], al, bh1 + 2);
    }

    // ---- Transpose into smT ----
    __syncthreads();
    float* smT = (float*)smem;   // [32][132] = 16896 B
    const int mi = lane >> 2;
    const int nf = (lane & 3) * 2;
    const int cw = 16 * w + mi;
#pragma unroll
    for (int t = 0; t < 4; t++) {
        smT[(8 * t + nf) * 132 + cw]         = acc[t][0];
        smT[(8 * t + nf + 1) * 132 + cw]     = acc[t][1];
        smT[(8 * t + nf) * 132 + cw + 8]     = acc[t][2];
        smT[(8 * t + nf + 1) * 132 + cw + 8] = acc[t][3];
    }
    __syncthreads();

    // ---- Edge correction (only 2 of 32 x-CTAs; uniform per CTA) ----
    const bool leftE  = (blockIdx.x == 0);
    const bool rightE = (blockIdx.x == gridDim.x - 1);
    if (leftE || rightE) {
        float* rext  = smT + 32 * 132;           // [32][64]
        float* yedge = rext + 32 * 64;           // [32][64]
        const int ybase = leftE ? 0 : (LDIM - 64);
        // stage edge y (fp32)
        for (int g = tid; g < 32 * 16; g += NTH) {
            int r = g >> 4, q = g & 15;
            *(float4*)(yedge + r * 64 + 4 * q) =
                *(const float4*)(y + (size_t)(r0 + r) * LDIM + ybase + 4 * q);
        }
        __syncthreads();
        // rext
        for (int g = tid; g < 32 * 64; g += NTH) {
            int r = g >> 6, mm = g & 63;
            float a = 0.0f;
            const float* yr = yedge + r * 64;
            if (leftE) {
                if (mm >= 1)
                    for (int j = 0; j <= 64 - mm; j++) a -= shH[j + mm + 63] * yr[j];
            } else {
                if (mm <= 62)
                    for (int t2 = 0; t2 <= 62 - mm; t2++) a -= shH[62 - mm - t2] * yr[63 - t2];
            }
            rext[r * 64 + mm] = a;
        }
        __syncthreads();
        // du applied into smT
        for (int g = tid; g < 32 * 64; g += NTH) {
            int r = g >> 6, k = g & 63;
            float d = 0.0f;
            const float* rr = rext + r * 64;
            if (leftE) {
                for (int mm = 1; mm <= 63 - k; mm++) d -= shH[64 + k + mm] * rr[mm];
                smT[r * 132 + k] += d;
            } else {
                int lim = (k < 62) ? k : 62;
                for (int mm = 0; mm <= lim; mm++) d -= shH[k - mm] * rr[mm];
                smT[r * 132 + 64 + k] += d;
            }
        }
        __syncthreads();
    }

    // ---- ISTA + coalesced float4 stores ----
    const float sv = __ldg(step);
    const int n = tid >> 3, cq = tid & 7;
    const float* srow = smT + n * 132 + 16 * cq;
    float4* orow = (float4*)(out + (size_t)(r0 + n) * LDIM + c0 + 16 * cq);
#pragma unroll
    for (int i = 0; i < 4; i++) {
        float a0 = sv * srow[4 * i + 0];
        float a1 = sv * srow[4 * i + 1];
        float a2 = sv * srow[4 * i + 2];
        float a3 = sv * srow[4 * i + 3];
        orow[i] = make_float4(
            copysignf(TITER * fmaxf(fabsf(a0) - LAMBDA, 0.0f), a0),
            copysignf(TITER * fmaxf(fabsf(a1) - LAMBDA, 0.0f), a1),
            copysignf(TITER * fmaxf(fabsf(a2) - LAMBDA, 0.0f), a2),
            copysignf(TITER * fmaxf(fabsf(a3) - LAMBDA, 0.0f), a3));
    }
}

extern "C" void kernel_launch(void* const* d_in, const int* in_sizes, int n_in,
                              void* d_out, int out_size)
{
    const float* y = nullptr;
    const float* h = nullptr;
    const float* s = nullptr;
    for (int i = 0; i < n_in; i++) {
        if (in_sizes[i] == BDIM * LDIM)      y = (const float*)d_in[i];
        else if (in_sizes[i] == KW)          h = (const float*)d_in[i];
        else if (in_sizes[i] == 1)           s = (const float*)d_in[i];
    }
    cudaFuncSetAttribute(ista_composed_kernel,
                         cudaFuncAttributeMaxDynamicSharedMemorySize, SM_TOTAL);
    dim3 grid(LDIM / COLS, BDIM / ROWS);   // (32, 128)
    ista_composed_kernel<<<grid, NTH, SM_TOTAL>>>(y, h, s, (float*)d_out);
}